// round 5
// baseline (speedup 1.0000x reference)
#include <cuda_runtime.h>
#include <cstdint>

#define T_SEQ 2048
#define NBATCH 64
#define NIN 16
#define NHEAD 8
#define HID 64
#define NGATE 256          // 4*HID gate rows per head
#define XP_ROW 2048        // NHEAD*NGATE floats per (t,b)

typedef unsigned long long u64;

// scratch (device globals; no runtime allocation)
__device__ float g_hist[(size_t)T_SEQ * NBATCH * NHEAD * HID];   // 256 MB
__device__ float g_xp[(size_t)T_SEQ * NBATCH * XP_ROW];          // 268 MB

// ---- packed fp32x2 helpers (fma.rn.f32x2 -> FFMA2) ----
__device__ __forceinline__ u64 ffma2(u64 a, u64 b, u64 c) {
    u64 d; asm("fma.rn.f32x2 %0, %1, %2, %3;" : "=l"(d) : "l"(a), "l"(b), "l"(c)); return d;
}
__device__ __forceinline__ u64 pack2(float lo, float hi) {
    u64 u; asm("mov.b64 %0, {%1, %2};" : "=l"(u) : "f"(lo), "f"(hi)); return u;
}
__device__ __forceinline__ float2 unpack2(u64 u) {
    float2 f; asm("mov.b64 {%0, %1}, %2;" : "=f"(f.x), "=f"(f.y) : "l"(u)); return f;
}
__device__ __forceinline__ float sigf(float z) {
    return __fdividef(1.0f, 1.0f + __expf(-z));
}
__device__ __forceinline__ float tanhf_fast(float z) {
    return fmaf(2.0f, sigf(2.0f * z), -1.0f);
}

// ============================================================================
// xp precompute (plain fp32 FMA, full chip):
//   g_xp[(t*64+b)*2048 + head*256 + r] = x[t,b,:]·W_ih[head,r,:] + b_ih + b_hh
// Grid: (8192 tb-tiles of 16 rows, 8 heads). Block: 256 (thread = gate row r).
// W row register-resident (8 u64); x tile broadcast from smem; 16 outs/thread.
// ============================================================================
__global__ __launch_bounds__(256) void xp_kernel(
    const float* __restrict__ x,     // (T,B,16)
    const float* __restrict__ W_ih,  // (8,256,16)
    const float* __restrict__ b_ih,  // (8,256)
    const float* __restrict__ b_hh)  // (8,256)
{
    __shared__ __align__(16) float xs[16][NIN];

    const int t    = threadIdx.x;          // gate row r
    const int tb0  = blockIdx.x * 16;      // first (t,b) row of tile
    const int head = blockIdx.y;

    // load x tile: 256 floats, one per thread (coalesced)
    xs[t >> 4][t & 15] = x[(size_t)tb0 * NIN + t];

    // W row into registers as 8 f32x2 pairs
    u64 w[8];
    {
        const ulonglong2* p = reinterpret_cast<const ulonglong2*>(
            W_ih + ((size_t)head * NGATE + t) * NIN);
#pragma unroll
        for (int k = 0; k < 4; ++k) { ulonglong2 v = p[k]; w[2 * k] = v.x; w[2 * k + 1] = v.y; }
    }
    const float bias = b_ih[head * NGATE + t] + b_hh[head * NGATE + t];
    __syncthreads();

    u64 acc[16];
#pragma unroll
    for (int m = 0; m < 16; ++m) acc[m] = 0ull;

#pragma unroll
    for (int k = 0; k < 8; ++k) {
        const u64 wk = w[k];
#pragma unroll
        for (int m = 0; m < 16; ++m) {
            u64 xv = reinterpret_cast<const u64*>(&xs[m][0])[k];   // broadcast LDS.64
            acc[m] = ffma2(wk, xv, acc[m]);
        }
    }

    float* dst = g_xp + (size_t)tb0 * XP_ROW + head * NGATE + t;
#pragma unroll
    for (int m = 0; m < 16; ++m) {
        float2 u = unpack2(acc[m]);
        dst[(size_t)m * XP_ROW] = u.x + u.y + bias;   // coalesced across threads
    }
}

// ============================================================================
// Recurrent kernel. Grid: 256 CTAs = head(8) x batch-pair(32). Block: 256.
// Thread t owns gate row t (both batches). z = xp(prefetched regs) + W_hh·h.
// Double-buffered hsb/zbuf by step parity; t>=128 uses bar.arrive at the
// z-exchange barrier and runs ahead to the next prefetch.
// ============================================================================
__global__ __launch_bounds__(256, 2) void lstm_rec_kernel(
    const float* __restrict__ W_hh)  // (8, 256, 64)
{
    const int t    = threadIdx.x;
    const int head = blockIdx.x >> 5;
    const int b0   = (blockIdx.x & 31) * 2;
    const int hr   = head * NGATE + t;

    u64 wh[32];
    {
        const ulonglong2* p = reinterpret_cast<const ulonglong2*>(W_hh + (size_t)hr * HID);
#pragma unroll
        for (int k = 0; k < 16; ++k) { ulonglong2 v = p[k]; wh[2 * k] = v.x; wh[2 * k + 1] = v.y; }
    }

    __shared__ __align__(16) float hsb[2][2][HID];        // [parity][batch][j]
    __shared__ __align__(16) float zbuf[2][2][64][4];     // [parity][batch][jj][gate]

    if (t < 128) { reinterpret_cast<float*>(hsb[0])[t] = 0.0f; }

    // xp prefetch (2 steps deep), coalesced across threads
    const float* xpp = g_xp + (size_t)b0 * XP_ROW + hr;
    const size_t XSTEP = (size_t)NBATCH * XP_ROW;         // 131072
    float xA0 = xpp[0],     xB0 = xpp[XP_ROW];
    float xA1 = xpp[XSTEP], xB1 = xpp[XSTEP + XP_ROW];

    const int gate = t >> 6;         // 0=i,1=f,2=g,3=o
    const int jj   = t & 63;
    const int bloc = gate & 1;       // consumer batch (t<128)
    float c = 0.0f;

    for (int ts = 0; ts < T_SEQ; ++ts) {
        const int p = ts & 1;
        const float cA = xA0, cB = xB0;
        xA0 = xA1; xB0 = xB1;
        {
            const int tn = (ts + 2 < T_SEQ) ? ts + 2 : T_SEQ - 1;
            const float* pf = xpp + (size_t)tn * XSTEP;
            xA1 = pf[0]; xB1 = pf[XP_ROW];
        }
        __syncthreads();                          // A: h(ts-1) in hsb[p] visible

        u64 a0a = pack2(cA, 0.0f), a1a = pack2(cB, 0.0f);
        u64 a0b = pack2(0.0f, 0.0f), a1b = a0b;

        const ulonglong2* h0 = reinterpret_cast<const ulonglong2*>(&hsb[p][0][0]);
        const ulonglong2* h1 = reinterpret_cast<const ulonglong2*>(&hsb[p][1][0]);
#pragma unroll
        for (int k = 0; k < 16; k += 2) {
            ulonglong2 p0 = h0[k], p1 = h1[k];
            a0a = ffma2(wh[2 * k],     p0.x, a0a);
            a0a = ffma2(wh[2 * k + 1], p0.y, a0a);
            a1a = ffma2(wh[2 * k],     p1.x, a1a);
            a1a = ffma2(wh[2 * k + 1], p1.y, a1a);
            ulonglong2 q0 = h0[k + 1], q1 = h1[k + 1];
            a0b = ffma2(wh[2 * k + 2], q0.x, a0b);
            a0b = ffma2(wh[2 * k + 3], q0.y, a0b);
            a1b = ffma2(wh[2 * k + 2], q1.x, a1b);
            a1b = ffma2(wh[2 * k + 3], q1.y, a1b);
        }
        float2 u0a = unpack2(a0a), u0b = unpack2(a0b);
        float2 u1a = unpack2(a1a), u1b = unpack2(a1b);
        zbuf[p][0][jj][gate] = (u0a.x + u0a.y) + (u0b.x + u0b.y);
        zbuf[p][1][jj][gate] = (u1a.x + u1a.y) + (u1b.x + u1b.y);

        if (t < 128) {
            asm volatile("bar.sync 1, 256;" ::: "memory");     // B: zbuf ready
            float4 z = *reinterpret_cast<float4*>(&zbuf[p][bloc][jj][0]);
            float iv = sigf(z.x);
            float fv = sigf(z.y);
            float gv = tanhf_fast(z.z);
            float ov = sigf(z.w);
            c = fmaf(fv, c, iv * gv);
            float h = ov * tanhf_fast(c);
            hsb[p ^ 1][bloc][jj] = h;
            g_hist[(((size_t)ts * NBATCH + b0 + bloc) * NHEAD + head) * HID + jj] = h;
        } else {
            asm volatile("bar.arrive 1, 256;" ::: "memory");   // non-blocking
        }
        // loop-top __syncthreads (A) publishes hsb[p^1] for step ts+1
    }
}

// ============================================================================
// Epilogue: out[t,b,h] = dot(h, W_lin[h]) + b_lin[h]; lstm_out = sum over heads
// ============================================================================
__global__ __launch_bounds__(256) void lstm_epi_kernel(
    const float* __restrict__ W_lin,
    const float* __restrict__ b_lin,
    float* __restrict__ out,
    float* __restrict__ lstm_out)
{
    const int cell = blockIdx.x * 16 + (threadIdx.x >> 4);
    const int q    = threadIdx.x & 15;

    const float4* hist4 = reinterpret_cast<const float4*>(g_hist) + (size_t)cell * 128;
    float4 v[NHEAD];
#pragma unroll
    for (int h = 0; h < NHEAD; ++h) v[h] = hist4[h * 16 + q];

    float4 s = v[0];
#pragma unroll
    for (int h = 1; h < NHEAD; ++h) { s.x += v[h].x; s.y += v[h].y; s.z += v[h].z; s.w += v[h].w; }
    reinterpret_cast<float4*>(lstm_out)[(size_t)cell * 16 + q] = s;

    const float4* wl4 = reinterpret_cast<const float4*>(W_lin);
    float d[NHEAD];
#pragma unroll
    for (int h = 0; h < NHEAD; ++h) {
        float4 w = wl4[h * 16 + q];
        float acc = v[h].x * w.x;
        acc = fmaf(v[h].y, w.y, acc);
        acc = fmaf(v[h].z, w.z, acc);
        acc = fmaf(v[h].w, w.w, acc);
        d[h] = acc;
    }
#pragma unroll
    for (int off = 8; off > 0; off >>= 1) {
#pragma unroll
        for (int h = 0; h < NHEAD; ++h)
            d[h] += __shfl_xor_sync(0xFFFFFFFFu, d[h], off);
    }
    if (q == 0) {
#pragma unroll
        for (int h = 0; h < NHEAD; ++h)
            out[(size_t)cell * NHEAD + h] = d[h] + b_lin[h];
    }
}

extern "C" void kernel_launch(void* const* d_in, const int* in_sizes, int n_in,
                              void* d_out, int out_size) {
    const float* x     = (const float*)d_in[0];
    const float* W_ih  = (const float*)d_in[1];
    const float* W_hh  = (const float*)d_in[2];
    const float* b_ih  = (const float*)d_in[3];
    const float* b_hh  = (const float*)d_in[4];
    const float* W_lin = (const float*)d_in[5];
    const float* b_lin = (const float*)d_in[6];

    float* out      = (float*)d_out;                         // (T,B,H)
    float* lstm_out = out + (size_t)T_SEQ * NBATCH * NHEAD;  // (T,B,HID)

    xp_kernel<<<dim3((T_SEQ * NBATCH) / 16, NHEAD), 256>>>(x, W_ih, b_ih, b_hh);
    lstm_rec_kernel<<<NHEAD * (NBATCH / 2), 256>>>(W_hh);
    lstm_epi_kernel<<<(T_SEQ * NBATCH) / 16, 256>>>(W_lin, b_lin, out, lstm_out);
}